// round 1
// baseline (speedup 1.0000x reference)
#include <cuda_runtime.h>
#include <cstdint>
#include <math.h>

#define N_NODES 100000
#define N_EDGES 1600000
#define F_IN    256
#define HID     64

// -------- scratch (no allocations allowed) --------
__device__ float g_deg [N_NODES];
__device__ float g_dinv[N_NODES];
__device__ float g_h   [(size_t)N_NODES * HID];   // h' = (x@W)*dinv  (current layer)
__device__ float g_x2  [(size_t)N_NODES * HID];   // activations / next-layer input
__device__ float g_s   [(size_t)N_NODES * HID];   // scatter accumulator
__device__ float g_h3  [(size_t)N_NODES * 2];
__device__ float g_s3  [(size_t)N_NODES * 2];

// -------------------- utility kernels --------------------
__global__ void k_init_deg(float* __restrict__ deg, int n) {
    int i = blockIdx.x * blockDim.x + threadIdx.x;
    if (i < n) deg[i] = 1.0f;               // self-loop contributes 1
}

__global__ void k_count_deg(const int* __restrict__ dst, float* __restrict__ deg, int e) {
    int i = blockIdx.x * blockDim.x + threadIdx.x;
    if (i < e) atomicAdd(&deg[dst[i]], 1.0f);
}

__global__ void k_dinv(const float* __restrict__ deg, float* __restrict__ dinv, int n) {
    int i = blockIdx.x * blockDim.x + threadIdx.x;
    if (i < n) dinv[i] = rsqrtf(deg[i]);
}

__global__ void k_zero4(float4* __restrict__ p, int n4) {
    int i = blockIdx.x * blockDim.x + threadIdx.x;
    if (i < n4) p[i] = make_float4(0.f, 0.f, 0.f, 0.f);
}

// -------------------- GEMM: out[m, 0:64] = (A[m,:] @ W[:,0:64]) * dinv[m] --------------------
// BM=64, BN=64 (full), BK=32; 256 threads; each thread 4x4 outputs.
__global__ void k_gemm_scale(const float* __restrict__ A, const float* __restrict__ W,
                             const float* __restrict__ dinv, float* __restrict__ out,
                             int M, int K) {
    __shared__ float As[64][33];   // [m][k], padded: conflict-free stores, broadcast reads
    __shared__ float Bs[32][64];   // [k][n]

    const int tid = threadIdx.x;
    const int tx  = tid & 15;      // col group (4 cols)
    const int ty  = tid >> 4;      // row group (4 rows)
    const int row0 = blockIdx.x * 64;

    float acc[4][4] = {};

    for (int k0 = 0; k0 < K; k0 += 32) {
        // load A tile 64x32 (float4 per thread, 2 rounds)
        #pragma unroll
        for (int l = 0; l < 2; l++) {
            int i  = tid + l * 256;          // 0..511 float4 slots
            int m  = i >> 3;                 // 8 float4 per row
            int kk = (i & 7) << 2;
            float4 v = make_float4(0.f, 0.f, 0.f, 0.f);
            int gr = row0 + m;
            if (gr < M) v = *(const float4*)(A + (size_t)gr * K + k0 + kk);
            As[m][kk + 0] = v.x; As[m][kk + 1] = v.y;
            As[m][kk + 2] = v.z; As[m][kk + 3] = v.w;
        }
        // load B tile 32x64
        #pragma unroll
        for (int l = 0; l < 2; l++) {
            int i  = tid + l * 256;
            int kk = i >> 4;                 // 16 float4 per row
            int n  = (i & 15) << 2;
            *(float4*)&Bs[kk][n] = *(const float4*)(W + (size_t)(k0 + kk) * 64 + n);
        }
        __syncthreads();

        #pragma unroll
        for (int kk = 0; kk < 32; kk++) {
            float a0 = As[ty * 4 + 0][kk];
            float a1 = As[ty * 4 + 1][kk];
            float a2 = As[ty * 4 + 2][kk];
            float a3 = As[ty * 4 + 3][kk];
            float4 b = *(float4*)&Bs[kk][tx * 4];
            acc[0][0] += a0 * b.x; acc[0][1] += a0 * b.y; acc[0][2] += a0 * b.z; acc[0][3] += a0 * b.w;
            acc[1][0] += a1 * b.x; acc[1][1] += a1 * b.y; acc[1][2] += a1 * b.z; acc[1][3] += a1 * b.w;
            acc[2][0] += a2 * b.x; acc[2][1] += a2 * b.y; acc[2][2] += a2 * b.z; acc[2][3] += a2 * b.w;
            acc[3][0] += a3 * b.x; acc[3][1] += a3 * b.y; acc[3][2] += a3 * b.z; acc[3][3] += a3 * b.w;
        }
        __syncthreads();
    }

    #pragma unroll
    for (int i = 0; i < 4; i++) {
        int gr = row0 + ty * 4 + i;
        if (gr < M) {
            float d = dinv[gr];
            float4 o = make_float4(acc[i][0] * d, acc[i][1] * d, acc[i][2] * d, acc[i][3] * d);
            *(float4*)(out + (size_t)gr * 64 + tx * 4) = o;
        }
    }
}

// -------------------- scatter: s[dst] += h'[src], 64 features, 16 threads/edge --------------------
__global__ void k_scatter64(const int* __restrict__ src, const int* __restrict__ dst,
                            const float* __restrict__ h, float* __restrict__ s, int e) {
    int idx = blockIdx.x * blockDim.x + threadIdx.x;
    if (idx >= e * 16) return;
    int ed = idx >> 4;
    int c  = (idx & 15) << 2;
    int sn = __ldg(&src[ed]);
    int dn = __ldg(&dst[ed]);
    float4 v = *(const float4*)(h + (size_t)sn * 64 + c);
    float* p = s + (size_t)dn * 64 + c;
    asm volatile("red.global.add.v4.f32 [%0], {%1, %2, %3, %4};"
                 :: "l"(p), "f"(v.x), "f"(v.y), "f"(v.z), "f"(v.w) : "memory");
}

// -------------------- epilogue: out = relu(dinv*(s + h') + b)  (self-loop folded in) ----------
__global__ void k_epi_relu(const float* __restrict__ s, const float* __restrict__ h,
                           const float* __restrict__ dinv, const float* __restrict__ b,
                           float* __restrict__ out, int n) {
    int idx = blockIdx.x * blockDim.x + threadIdx.x;
    if (idx >= n * 16) return;
    int i = idx >> 4;
    int c = (idx & 15) << 2;
    float d = dinv[i];
    float4 sv = *(const float4*)(s + (size_t)i * 64 + c);
    float4 hv = *(const float4*)(h + (size_t)i * 64 + c);
    float4 bv = *(const float4*)(b + c);
    float4 o;
    o.x = fmaxf(d * (sv.x + hv.x) + bv.x, 0.f);
    o.y = fmaxf(d * (sv.y + hv.y) + bv.y, 0.f);
    o.z = fmaxf(d * (sv.z + hv.z) + bv.z, 0.f);
    o.w = fmaxf(d * (sv.w + hv.w) + bv.w, 0.f);
    *(float4*)(out + (size_t)i * 64 + c) = o;
}

// -------------------- layer 3: h3'[m, 0:2] = (A[m,:] @ W3) * dinv[m] --------------------
__global__ void k_gemm3(const float* __restrict__ A, const float* __restrict__ W3,
                        const float* __restrict__ dinv, float* __restrict__ out, int M) {
    __shared__ float w[128];
    if (threadIdx.x < 128) w[threadIdx.x] = W3[threadIdx.x];
    __syncthreads();
    int r = blockIdx.x * blockDim.x + threadIdx.x;
    if (r >= M) return;
    const float* ap = A + (size_t)r * 64;
    float a0 = 0.f, a1 = 0.f;
    #pragma unroll
    for (int k4 = 0; k4 < 64; k4 += 4) {
        float4 a = *(const float4*)(ap + k4);
        a0 += a.x * w[2 * k4 + 0] + a.y * w[2 * k4 + 2] + a.z * w[2 * k4 + 4] + a.w * w[2 * k4 + 6];
        a1 += a.x * w[2 * k4 + 1] + a.y * w[2 * k4 + 3] + a.z * w[2 * k4 + 5] + a.w * w[2 * k4 + 7];
    }
    float d = dinv[r];
    out[2 * r + 0] = a0 * d;
    out[2 * r + 1] = a1 * d;
}

__global__ void k_scatter2(const int* __restrict__ src, const int* __restrict__ dst,
                           const float* __restrict__ h3, float* __restrict__ s3, int e) {
    int i = blockIdx.x * blockDim.x + threadIdx.x;
    if (i >= e) return;
    int sn = __ldg(&src[i]);
    int dn = __ldg(&dst[i]);
    float2 v = *(const float2*)(h3 + (size_t)sn * 2);
    float* p = s3 + (size_t)dn * 2;
    asm volatile("red.global.add.v2.f32 [%0], {%1, %2};"
                 :: "l"(p), "f"(v.x), "f"(v.y) : "memory");
}

__global__ void k_final(const float* __restrict__ s3, const float* __restrict__ h3,
                        const float* __restrict__ dinv, const float* __restrict__ b3,
                        float* __restrict__ out, int n) {
    int i = blockIdx.x * blockDim.x + threadIdx.x;
    if (i >= n) return;
    float d  = dinv[i];
    float o0 = d * (s3[2 * i + 0] + h3[2 * i + 0]) + b3[0];
    float o1 = d * (s3[2 * i + 1] + h3[2 * i + 1]) + b3[1];
    float m  = fmaxf(o0, o1);
    float lse = m + logf(expf(o0 - m) + expf(o1 - m));
    out[2 * i + 0] = o0 - lse;
    out[2 * i + 1] = o1 - lse;
}

// -------------------- launch --------------------
extern "C" void kernel_launch(void* const* d_in, const int* in_sizes, int n_in,
                              void* d_out, int out_size) {
    const float* x  = (const float*)d_in[0];
    const int*   ei = (const int*)  d_in[1];
    const float* W1 = (const float*)d_in[2];
    const float* b1 = (const float*)d_in[3];
    const float* W2 = (const float*)d_in[4];
    const float* b2 = (const float*)d_in[5];
    const float* W3 = (const float*)d_in[6];
    const float* b3 = (const float*)d_in[7];

    const int N = in_sizes[0] / F_IN;
    const int E = in_sizes[1] / 2;
    const int* src = ei;
    const int* dst = ei + E;

    float *deg, *dinv, *h, *x2, *s, *h3, *s3;
    cudaGetSymbolAddress((void**)&deg,  g_deg);
    cudaGetSymbolAddress((void**)&dinv, g_dinv);
    cudaGetSymbolAddress((void**)&h,    g_h);
    cudaGetSymbolAddress((void**)&x2,   g_x2);
    cudaGetSymbolAddress((void**)&s,    g_s);
    cudaGetSymbolAddress((void**)&h3,   g_h3);
    cudaGetSymbolAddress((void**)&s3,   g_s3);

    const int T = 256;
    const int gemm_blocks = (N + 63) / 64;
    const int nf4  = N * 16;           // N*64/4 float4
    const int nthE = E * 16;           // scatter threads

    // degree + dinv
    k_init_deg <<<(N + T - 1) / T, T>>>(deg, N);
    k_count_deg<<<(E + T - 1) / T, T>>>(dst, deg, E);
    k_dinv     <<<(N + T - 1) / T, T>>>(deg, dinv, N);

    // ---- layer 1 ----
    k_gemm_scale<<<gemm_blocks, T>>>(x, W1, dinv, h, N, F_IN);
    k_zero4     <<<(nf4 + T - 1) / T, T>>>((float4*)s, nf4);
    k_scatter64 <<<(nthE + T - 1) / T, T>>>(src, dst, h, s, E);
    k_epi_relu  <<<(N * 16 + T - 1) / T, T>>>(s, h, dinv, b1, x2, N);

    // ---- layer 2 ----
    k_gemm_scale<<<gemm_blocks, T>>>(x2, W2, dinv, h, N, HID);
    k_zero4     <<<(nf4 + T - 1) / T, T>>>((float4*)s, nf4);
    k_scatter64 <<<(nthE + T - 1) / T, T>>>(src, dst, h, s, E);
    k_epi_relu  <<<(N * 16 + T - 1) / T, T>>>(s, h, dinv, b2, x2, N);

    // ---- layer 3 ----
    k_gemm3   <<<(N + T - 1) / T, T>>>(x2, W3, dinv, h3, N);
    k_zero4   <<<(N / 2 + T - 1) / T, T>>>((float4*)s3, N / 2);
    k_scatter2<<<(E + T - 1) / T, T>>>(src, dst, h3, s3, E);
    k_final   <<<(N + T - 1) / T, T>>>(s3, h3, dinv, b3, (float*)d_out, N);
}

// round 2
// speedup vs baseline: 1.4771x; 1.4771x over previous
#include <cuda_runtime.h>
#include <cstdint>
#include <math.h>

#define N_NODES 100000
#define N_EDGES 1600000
#define F_IN    256
#define HID     64

// -------- scratch (no allocations allowed) --------
__device__ int   g_degi  [N_NODES];
__device__ float g_dinv  [N_NODES];
__device__ int   g_rstart[N_NODES];
__device__ int   g_cursor[N_NODES];
__device__ int   g_bsum  [512];
__device__ int   g_csr   [N_EDGES];
__device__ float g_h     [(size_t)N_NODES * HID];   // h' = (x@W)*dinv (current layer)
__device__ float g_x2    [(size_t)N_NODES * HID];   // activations / next-layer input
__device__ float g_h3    [(size_t)N_NODES * 2];

// -------------------- degree / dinv --------------------
__global__ void k_zero_deg(int* __restrict__ deg, int n) {
    int i = blockIdx.x * blockDim.x + threadIdx.x;
    if (i < n) deg[i] = 0;
}

__global__ void k_count_deg(const int* __restrict__ dst, int* __restrict__ deg, int e) {
    int i = blockIdx.x * blockDim.x + threadIdx.x;
    if (i < e) atomicAdd(&deg[dst[i]], 1);
}

__global__ void k_dinv(const int* __restrict__ deg, float* __restrict__ dinv, int n) {
    int i = blockIdx.x * blockDim.x + threadIdx.x;
    if (i < n) dinv[i] = rsqrtf((float)(deg[i] + 1));   // +1 self-loop
}

// -------------------- two-level exclusive scan over deg --------------------
__global__ void k_scan_block(const int* __restrict__ deg, int* __restrict__ rstart,
                             int* __restrict__ bsum, int n) {
    __shared__ int sm[256];
    int i = blockIdx.x * 256 + threadIdx.x;
    int v = (i < n) ? deg[i] : 0;
    sm[threadIdx.x] = v;
    __syncthreads();
    #pragma unroll
    for (int off = 1; off < 256; off <<= 1) {
        int t = (threadIdx.x >= off) ? sm[threadIdx.x - off] : 0;
        __syncthreads();
        sm[threadIdx.x] += t;
        __syncthreads();
    }
    if (i < n) rstart[i] = sm[threadIdx.x] - v;       // exclusive
    if (threadIdx.x == 255) bsum[blockIdx.x] = sm[255];
}

__global__ void k_scan_sums(int* __restrict__ bsum, int nb) {   // 1 block, 512 threads
    __shared__ int sm[512];
    int v = (threadIdx.x < nb) ? bsum[threadIdx.x] : 0;
    sm[threadIdx.x] = v;
    __syncthreads();
    #pragma unroll
    for (int off = 1; off < 512; off <<= 1) {
        int t = (threadIdx.x >= off) ? sm[threadIdx.x - off] : 0;
        __syncthreads();
        sm[threadIdx.x] += t;
        __syncthreads();
    }
    if (threadIdx.x < nb) bsum[threadIdx.x] = sm[threadIdx.x] - v;  // exclusive
}

__global__ void k_add_off(int* __restrict__ rstart, int* __restrict__ cursor,
                          const int* __restrict__ bsum, int n) {
    int i = blockIdx.x * blockDim.x + threadIdx.x;
    if (i < n) {
        int v = rstart[i] + bsum[i >> 8];
        rstart[i] = v;
        cursor[i] = v;
    }
}

__global__ void k_build_csr(const int* __restrict__ src, const int* __restrict__ dst,
                            int* __restrict__ cursor, int* __restrict__ csr, int e) {
    int i = blockIdx.x * blockDim.x + threadIdx.x;
    if (i < e) {
        int p = atomicAdd(&cursor[dst[i]], 1);
        csr[p] = src[i];
    }
}

// -------------------- GEMM: out[m, 0:64] = (A[m,:] @ W[:,0:64]) * dinv[m] --------------------
// BM=64, BN=64, BK=32; 256 threads; 4x4 per thread; A tile stored transposed [k][m].
__global__ void k_gemm_scale(const float* __restrict__ A, const float* __restrict__ W,
                             const float* __restrict__ dinv, float* __restrict__ out,
                             int M, int K) {
    __shared__ float As[32][68];   // [k][m], pad 68: float4-aligned reads
    __shared__ float Bs[32][64];   // [k][n]

    const int tid = threadIdx.x;
    const int tx  = tid & 15;      // col group (4 cols)
    const int ty  = tid >> 4;      // row group (4 rows)
    const int row0 = blockIdx.x * 64;

    float acc[4][4] = {};

    for (int k0 = 0; k0 < K; k0 += 32) {
        // load A tile 64x32 -> transposed store As[k][m]
        #pragma unroll
        for (int l = 0; l < 2; l++) {
            int i  = tid + l * 256;          // 0..511 float4 slots
            int m  = i >> 3;                 // 8 float4 per row
            int kk = (i & 7) << 2;
            float4 v = make_float4(0.f, 0.f, 0.f, 0.f);
            int gr = row0 + m;
            if (gr < M) v = *(const float4*)(A + (size_t)gr * K + k0 + kk);
            As[kk + 0][m] = v.x; As[kk + 1][m] = v.y;
            As[kk + 2][m] = v.z; As[kk + 3][m] = v.w;
        }
        // load B tile 32x64
        #pragma unroll
        for (int l = 0; l < 2; l++) {
            int i  = tid + l * 256;
            int kk = i >> 4;                 // 16 float4 per row
            int n  = (i & 15) << 2;
            *(float4*)&Bs[kk][n] = *(const float4*)(W + (size_t)(k0 + kk) * 64 + n);
        }
        __syncthreads();

        #pragma unroll
        for (int kk = 0; kk < 32; kk++) {
            float4 a = *(float4*)&As[kk][ty * 4];
            float4 b = *(float4*)&Bs[kk][tx * 4];
            acc[0][0] += a.x * b.x; acc[0][1] += a.x * b.y; acc[0][2] += a.x * b.z; acc[0][3] += a.x * b.w;
            acc[1][0] += a.y * b.x; acc[1][1] += a.y * b.y; acc[1][2] += a.y * b.z; acc[1][3] += a.y * b.w;
            acc[2][0] += a.z * b.x; acc[2][1] += a.z * b.y; acc[2][2] += a.z * b.z; acc[2][3] += a.z * b.w;
            acc[3][0] += a.w * b.x; acc[3][1] += a.w * b.y; acc[3][2] += a.w * b.z; acc[3][3] += a.w * b.w;
        }
        __syncthreads();
    }

    #pragma unroll
    for (int i = 0; i < 4; i++) {
        int gr = row0 + ty * 4 + i;
        if (gr < M) {
            float d = dinv[gr];
            float4 o = make_float4(acc[i][0] * d, acc[i][1] * d, acc[i][2] * d, acc[i][3] * d);
            *(float4*)(out + (size_t)gr * 64 + tx * 4) = o;
        }
    }
}

// -------------------- pull aggregation + fused epilogue (64 features) --------------------
// 16 threads per node, 4 features each. out = relu(dinv*(sum_in h'[u] + h'[i]) + b)
__global__ void k_pull64(const int* __restrict__ rstart, const int* __restrict__ degi,
                         const int* __restrict__ csr, const float* __restrict__ h,
                         const float* __restrict__ dinv, const float* __restrict__ b,
                         float* __restrict__ out, int n) {
    int gid  = blockIdx.x * blockDim.x + threadIdx.x;
    int node = gid >> 4;
    if (node >= n) return;
    int c = (gid & 15) << 2;

    int s0  = __ldg(&rstart[node]);
    int cnt = __ldg(&degi[node]);

    float4 acc = *(const float4*)(h + (size_t)node * 64 + c);   // self-loop term

    int u = (cnt > 0) ? __ldg(&csr[s0]) : 0;
    for (int e = 0; e < cnt; e++) {
        int unext = (e + 1 < cnt) ? __ldg(&csr[s0 + e + 1]) : 0;
        float4 v = *(const float4*)(h + (size_t)u * 64 + c);
        acc.x += v.x; acc.y += v.y; acc.z += v.z; acc.w += v.w;
        u = unext;
    }

    float d = dinv[node];
    float4 bb = *(const float4*)(b + c);
    float4 o;
    o.x = fmaxf(d * acc.x + bb.x, 0.f);
    o.y = fmaxf(d * acc.y + bb.y, 0.f);
    o.z = fmaxf(d * acc.z + bb.z, 0.f);
    o.w = fmaxf(d * acc.w + bb.w, 0.f);
    *(float4*)(out + (size_t)node * 64 + c) = o;
}

// -------------------- layer 3: h3'[m, 0:2] = (A[m,:] @ W3) * dinv[m] --------------------
__global__ void k_gemm3(const float* __restrict__ A, const float* __restrict__ W3,
                        const float* __restrict__ dinv, float* __restrict__ out, int M) {
    __shared__ float w[128];
    if (threadIdx.x < 128) w[threadIdx.x] = W3[threadIdx.x];
    __syncthreads();
    int r = blockIdx.x * blockDim.x + threadIdx.x;
    if (r >= M) return;
    const float* ap = A + (size_t)r * 64;
    float a0 = 0.f, a1 = 0.f;
    #pragma unroll
    for (int k4 = 0; k4 < 64; k4 += 4) {
        float4 a = *(const float4*)(ap + k4);
        a0 += a.x * w[2 * k4 + 0] + a.y * w[2 * k4 + 2] + a.z * w[2 * k4 + 4] + a.w * w[2 * k4 + 6];
        a1 += a.x * w[2 * k4 + 1] + a.y * w[2 * k4 + 3] + a.z * w[2 * k4 + 5] + a.w * w[2 * k4 + 7];
    }
    float d = dinv[r];
    out[2 * r + 0] = a0 * d;
    out[2 * r + 1] = a1 * d;
}

// -------------------- layer 3: pull (2 feats) + log_softmax, 1 thread/node --------------------
__global__ void k_pull2_final(const int* __restrict__ rstart, const int* __restrict__ degi,
                              const int* __restrict__ csr, const float* __restrict__ h3,
                              const float* __restrict__ dinv, const float* __restrict__ b3,
                              float* __restrict__ out, int n) {
    int i = blockIdx.x * blockDim.x + threadIdx.x;
    if (i >= n) return;
    int s0  = __ldg(&rstart[i]);
    int cnt = __ldg(&degi[i]);

    float2 self = *(const float2*)(h3 + (size_t)i * 2);
    float a0 = self.x, a1 = self.y;

    int u = (cnt > 0) ? __ldg(&csr[s0]) : 0;
    for (int e = 0; e < cnt; e++) {
        int unext = (e + 1 < cnt) ? __ldg(&csr[s0 + e + 1]) : 0;
        float2 v = *(const float2*)(h3 + (size_t)u * 2);
        a0 += v.x; a1 += v.y;
        u = unext;
    }

    float d  = dinv[i];
    float o0 = d * a0 + b3[0];
    float o1 = d * a1 + b3[1];
    float m  = fmaxf(o0, o1);
    float lse = m + logf(expf(o0 - m) + expf(o1 - m));
    out[2 * i + 0] = o0 - lse;
    out[2 * i + 1] = o1 - lse;
}

// -------------------- launch --------------------
extern "C" void kernel_launch(void* const* d_in, const int* in_sizes, int n_in,
                              void* d_out, int out_size) {
    const float* x  = (const float*)d_in[0];
    const int*   ei = (const int*)  d_in[1];
    const float* W1 = (const float*)d_in[2];
    const float* b1 = (const float*)d_in[3];
    const float* W2 = (const float*)d_in[4];
    const float* b2 = (const float*)d_in[5];
    const float* W3 = (const float*)d_in[6];
    const float* b3 = (const float*)d_in[7];

    const int N = in_sizes[0] / F_IN;
    const int E = in_sizes[1] / 2;
    const int* src = ei;
    const int* dst = ei + E;

    int *degi, *rstart, *cursor, *bsum, *csr;
    float *dinv, *h, *x2, *h3;
    cudaGetSymbolAddress((void**)&degi,   g_degi);
    cudaGetSymbolAddress((void**)&rstart, g_rstart);
    cudaGetSymbolAddress((void**)&cursor, g_cursor);
    cudaGetSymbolAddress((void**)&bsum,   g_bsum);
    cudaGetSymbolAddress((void**)&csr,    g_csr);
    cudaGetSymbolAddress((void**)&dinv,   g_dinv);
    cudaGetSymbolAddress((void**)&h,      g_h);
    cudaGetSymbolAddress((void**)&x2,     g_x2);
    cudaGetSymbolAddress((void**)&h3,     g_h3);

    const int T  = 256;
    const int NB = (N + 255) / 256;          // scan blocks (391)
    const int gemm_blocks = (N + 63) / 64;
    const int pull_blocks = (N * 16 + T - 1) / T;

    // ---- graph preprocessing: degree, dinv, CSR ----
    k_zero_deg  <<<(N + T - 1) / T, T>>>(degi, N);
    k_count_deg <<<(E + T - 1) / T, T>>>(dst, degi, E);
    k_dinv      <<<(N + T - 1) / T, T>>>(degi, dinv, N);
    k_scan_block<<<NB, 256>>>(degi, rstart, bsum, N);
    k_scan_sums <<<1, 512>>>(bsum, NB);
    k_add_off   <<<(N + T - 1) / T, T>>>(rstart, cursor, bsum, N);
    k_build_csr <<<(E + T - 1) / T, T>>>(src, dst, cursor, csr, E);

    // ---- layer 1 ----
    k_gemm_scale<<<gemm_blocks, T>>>(x, W1, dinv, h, N, F_IN);
    k_pull64    <<<pull_blocks, T>>>(rstart, degi, csr, h, dinv, b1, x2, N);

    // ---- layer 2 ----
    k_gemm_scale<<<gemm_blocks, T>>>(x2, W2, dinv, h, N, HID);
    k_pull64    <<<pull_blocks, T>>>(rstart, degi, csr, h, dinv, b2, x2, N);

    // ---- layer 3 ----
    k_gemm3     <<<(N + T - 1) / T, T>>>(x2, W3, dinv, h3, N);
    k_pull2_final<<<(N + T - 1) / T, T>>>(rstart, degi, csr, h3, dinv, b3, (float*)d_out, N);
}